// round 12
// baseline (speedup 1.0000x reference)
#include <cuda_runtime.h>
#include <cstdint>

// ---------------------------------------------------------------------------
// BCNet, tf32 mma.sync. k-perm = 8x4 transpose within each 32-float block
// (k = 4*j + t <-> kappa = 8*t + j) on both operands -> LDS.128 fragments.
// R11: CTA tile 128x256, 8 warps of 64x64 (128 acc regs, no reg cap),
//      R8 pipeline order restored (prefetch BEFORE compute, 2 barriers),
//      fast vectorized perm passes (R10).
// ---------------------------------------------------------------------------

#define B_   32
#define NV_  512
#define NQ_  128
#define VD_  2048
#define QD_  1024
#define HK_  1536
#define HO_  8

__device__ float g_at [(size_t)B_ * NV_ * VD_];      // perm/cvt v      134MB
__device__ float g_qt [(size_t)B_ * NQ_ * QD_];      // perm/cvt q       17MB
__device__ float g_wvt[(size_t)HK_ * VD_];           // perm/cvt Wv      13MB
__device__ float g_wqt[(size_t)HK_ * QD_];           // perm/cvt Wq       6MB
__device__ float g_v  [(size_t)B_ * NV_ * HK_];      // G1 out plain    100MB
__device__ float g_vtp[(size_t)B_ * NV_ * HK_];      // perm/cvt g_v    100MB
__device__ float g_q  [(size_t)B_ * NQ_ * HK_];      // G2 out plain     25MB
__device__ float g_qh [(size_t)B_ * HO_ * NQ_ * HK_];// perm(q*hm)      201MB

#define BM 128
#define BN 256
#define KT 32
#define PROW 144                      // smem row stride bytes (36 floats)
#define A_BYTES (BM * PROW)           // 18432
#define B_BYTES (BN * PROW)           // 36864
#define STAGE_BYTES (A_BYTES + B_BYTES) // 55296
#define NSTAGE 3
#define SMEM_BYTES (NSTAGE * STAGE_BYTES)   // 165888

__device__ __forceinline__ uint32_t rna(float x) {
    uint32_t y; asm("cvt.rna.tf32.f32 %0, %1;" : "=r"(y) : "f"(x)); return y;
}
__device__ __forceinline__ uint32_t smem_u32(const void* p) {
    uint32_t a;
    asm("{ .reg .u64 t; cvta.to.shared.u64 t, %1; cvt.u32.u64 %0, t; }"
        : "=r"(a) : "l"(p));
    return a;
}
__device__ __forceinline__ void cpa16(uint32_t dst, const void* src) {
    asm volatile("cp.async.cg.shared.global [%0], [%1], 16;"
                 :: "r"(dst), "l"(src) : "memory");
}
__device__ __forceinline__ void cpa_commit() {
    asm volatile("cp.async.commit_group;" ::: "memory");
}
__device__ __forceinline__ void cpa_wait1() {
    asm volatile("cp.async.wait_group 1;" ::: "memory");
}
__device__ __forceinline__ void mma8(float& d0, float& d1, float& d2, float& d3,
                                     uint32_t a0, uint32_t a1, uint32_t a2, uint32_t a3,
                                     uint32_t b0, uint32_t b1) {
    asm volatile(
        "mma.sync.aligned.m16n8k8.row.col.f32.tf32.tf32.f32 "
        "{%0,%1,%2,%3}, {%4,%5,%6,%7}, {%8,%9}, {%0,%1,%2,%3};"
        : "+f"(d0), "+f"(d1), "+f"(d2), "+f"(d3)
        : "r"(a0), "r"(a1), "r"(a2), "r"(a3), "r"(b0), "r"(b1));
}

// --------------- pre-pass: vectorized 8x4 block transpose + cvt -----------
// dsel: 0->g_at, 1->g_qt, 2->g_wvt, 3->g_wqt, 4->g_vtp(src=g_v)
__global__ void __launch_bounds__(256)
perm_cvt(const float* __restrict__ src_in, int dsel, size_t nblk)
{
    const size_t idx = (size_t)blockIdx.x * blockDim.x + threadIdx.x;
    if (idx >= nblk) return;
    const float* __restrict__ src = (dsel == 4) ? g_v : src_in;
    float* __restrict__ dstf =
        (dsel == 0) ? g_at : (dsel == 1) ? g_qt :
        (dsel == 2) ? g_wvt : (dsel == 3) ? g_wqt : g_vtp;

    const float4* __restrict__ s = (const float4*)src + idx * 8;
    float rr[32];
#pragma unroll
    for (int j = 0; j < 8; ++j) {
        const float4 t4 = s[j];
        rr[4 * j + 0] = t4.x; rr[4 * j + 1] = t4.y;
        rr[4 * j + 2] = t4.z; rr[4 * j + 3] = t4.w;
    }
    uint4* __restrict__ d = (uint4*)dstf + idx * 8;
#pragma unroll
    for (int t = 0; t < 4; ++t) {
#pragma unroll
        for (int b = 0; b < 2; ++b) {
            uint4 o;
            o.x = rna(rr[(4 * b + 0) * 4 + t]);
            o.y = rna(rr[(4 * b + 1) * 4 + t]);
            o.z = rna(rr[(4 * b + 2) * 4 + t]);
            o.w = rna(rr[(4 * b + 3) * 4 + t]);
            d[t * 2 + b] = o;
        }
    }
}

// ---- qh pass: g_qh[(z*8+h)*128+q] = perm(rna(g_q[z*128+q] * h_mat[h])) ----
__global__ void __launch_bounds__(256)
qh_cvt(const float* __restrict__ h_mat)
{
    const size_t nblk = (size_t)B_ * HO_ * NQ_ * (HK_ / 32);
    const size_t idx = (size_t)blockIdx.x * blockDim.x + threadIdx.x;
    if (idx >= nblk) return;
    const int BPR = HK_ / 32;
    const size_t row = idx / BPR;
    const int blk = (int)(idx % BPR);
    const int q = (int)(row & 127);
    const int h = (int)((row >> 7) & 7);
    const int z = (int)(row >> 10);

    const float4* __restrict__ s = (const float4*)
        (g_q + ((size_t)z * NQ_ + q) * HK_) + blk * 8;
    const float4* __restrict__ hm = (const float4*)
        (h_mat + (size_t)h * HK_) + blk * 8;

    float rr[32];
#pragma unroll
    for (int j = 0; j < 8; ++j) {
        const float4 a = s[j];
        const float4 m = hm[j];
        rr[4 * j + 0] = a.x * m.x; rr[4 * j + 1] = a.y * m.y;
        rr[4 * j + 2] = a.z * m.z; rr[4 * j + 3] = a.w * m.w;
    }
    uint4* __restrict__ d = (uint4*)(g_qh + row * HK_) + blk * 8;
#pragma unroll
    for (int t = 0; t < 4; ++t) {
#pragma unroll
        for (int b = 0; b < 2; ++b) {
            uint4 o;
            o.x = rna(rr[(4 * b + 0) * 4 + t]);
            o.y = rna(rr[(4 * b + 1) * 4 + t]);
            o.z = rna(rr[(4 * b + 2) * 4 + t]);
            o.w = rna(rr[(4 * b + 3) * 4 + t]);
            d[t * 2 + b] = o;
        }
    }
}

// ------------------------------ GEMM kernel -------------------------------
// CTA 128x256, 8 warps of 64x64: warp_m=(wid&1)*64, warp_n=(wid>>1)*64.
// sel0: A=g_at,B=g_wvt -> g_v plain (relu+bias)
// sel1: A=g_qt,B=g_wqt -> g_q plain (relu+bias)
// sel2: A=g_vtp[z],B=g_qh[z] -> Cp (+h_bias[h]); warp's 64-col window is
//       inside one 128-block, so h is constant per warp.
__global__ void __launch_bounds__(256)
gemm_mma(const float* __restrict__ bias, const float* __restrict__ h_bias,
         float* __restrict__ Cp, int Ntot, int K, int sel)
{
    extern __shared__ char smem[];
    const uint32_t smb = smem_u32(smem);

    const int tid   = threadIdx.x;
    const int wid   = tid >> 5;
    const int lane  = tid & 31;
    const int group = lane >> 2;
    const int tig   = lane & 3;
    const int warp_m = (wid & 1) * 64;
    const int warp_n = (wid >> 1) * 64;

    const int bm = blockIdx.x * BM;
    const int bn = blockIdx.y * BN;
    const int z  = blockIdx.z;
    const int mode = (sel == 2);

    const float* __restrict__ Abase =
        (sel == 0) ? g_at : (sel == 1) ? g_qt : g_vtp;
    const float* __restrict__ Bbase =
        (sel == 0) ? g_wvt : (sel == 1) ? g_wqt : g_qh;

    const float* __restrict__ Ag = Abase +
        ((size_t)(mode ? z * NV_ : 0) + bm) * K;
    const float* __restrict__ Bg = Bbase +
        ((size_t)(mode ? z * (HO_ * NQ_) : 0) + bn) * K;

    const int r0 = tid >> 3;                  // 0..31
    const int s4 = (tid & 7) * 4;             // segment (floats)
    const uint32_t stg_off = (uint32_t)(r0 * PROW + s4 * 4);

    float acc[4][8][4];
#pragma unroll
    for (int i = 0; i < 4; ++i)
#pragma unroll
        for (int j = 0; j < 8; ++j)
#pragma unroll
            for (int l = 0; l < 4; ++l) acc[i][j][l] = 0.f;

    const int NC = K / KT;

    // prologue: stages 0 and 1
#pragma unroll
    for (int s = 0; s < 2; ++s) {
        const uint32_t sb = smb + s * STAGE_BYTES;
        const int k0 = s * KT;
#pragma unroll
        for (int i = 0; i < 4; ++i) {         // A: 128 rows
            const int r = r0 + 32 * i;
            cpa16(sb + stg_off + i * 32 * PROW, Ag + (size_t)r * K + k0 + s4);
        }
#pragma unroll
        for (int i = 0; i < 8; ++i) {         // B: 256 rows
            const int r = r0 + 32 * i;
            cpa16(sb + A_BYTES + stg_off + i * 32 * PROW,
                  Bg + (size_t)r * K + k0 + s4);
        }
        cpa_commit();
    }

    const int tb = tig * 32;

    for (int c = 0; c < NC; ++c) {
        cpa_wait1();
        __syncthreads();

        // prefetch stage c+2 FIRST (max latency hiding)
        if (c + 2 < NC) {
            const uint32_t sb = smb + ((c + 2) % NSTAGE) * STAGE_BYTES;
            const int k0 = (c + 2) * KT;
#pragma unroll
            for (int i = 0; i < 4; ++i) {
                const int r = r0 + 32 * i;
                cpa16(sb + stg_off + i * 32 * PROW,
                      Ag + (size_t)r * K + k0 + s4);
            }
#pragma unroll
            for (int i = 0; i < 8; ++i) {
                const int r = r0 + 32 * i;
                cpa16(sb + A_BYTES + stg_off + i * 32 * PROW,
                      Bg + (size_t)r * K + k0 + s4);
            }
        }
        cpa_commit();

        const char* sa = smem + (c % NSTAGE) * STAGE_BYTES;
        const char* sbuf = sa + A_BYTES;
#pragma unroll
        for (int hf = 0; hf < 2; ++hf) {
            const int hb = hf * 16;
            uint4 aL[4], aH[4];
#pragma unroll
            for (int mf = 0; mf < 4; ++mf) {
                const int m = warp_m + mf * 16 + group;
                aL[mf] = *(const uint4*)(sa + m * PROW + tb + hb);
                aH[mf] = *(const uint4*)(sa + (m + 8) * PROW + tb + hb);
            }
#pragma unroll
            for (int nf = 0; nf < 8; ++nf) {
                const uint4 bv = *(const uint4*)(sbuf +
                    (warp_n + nf * 8 + group) * PROW + tb + hb);
#pragma unroll
                for (int mf = 0; mf < 4; ++mf) {
                    mma8(acc[mf][nf][0], acc[mf][nf][1],
                         acc[mf][nf][2], acc[mf][nf][3],
                         aL[mf].x, aH[mf].x, aL[mf].y, aH[mf].y,
                         bv.x, bv.y);
                    mma8(acc[mf][nf][0], acc[mf][nf][1],
                         acc[mf][nf][2], acc[mf][nf][3],
                         aL[mf].z, aH[mf].z, aL[mf].w, aH[mf].w,
                         bv.z, bv.w);
                }
            }
        }
        __syncthreads();
    }

    // ---------------------------- epilogue --------------------------------
    if (!mode) {
        float* __restrict__ C = (sel == 0) ? g_v : g_q;
#pragma unroll
        for (int nf = 0; nf < 8; ++nf) {
            const int gn = bn + warp_n + nf * 8 + 2 * tig;
            const float b0 = __ldg(&bias[gn]);
            const float b1 = __ldg(&bias[gn + 1]);
#pragma unroll
            for (int mf = 0; mf < 4; ++mf) {
                const int gm = bm + warp_m + mf * 16 + group;
                float2 lo, hi;
                lo.x = fmaxf(acc[mf][nf][0] + b0, 0.f);
                lo.y = fmaxf(acc[mf][nf][1] + b1, 0.f);
                hi.x = fmaxf(acc[mf][nf][2] + b0, 0.f);
                hi.y = fmaxf(acc[mf][nf][3] + b1, 0.f);
                *(float2*)(C + (size_t)gm * Ntot + gn)       = lo;
                *(float2*)(C + (size_t)(gm + 8) * Ntot + gn) = hi;
            }
        }
    } else {
        const int h = (bn + warp_n) >> 7;          // constant per warp
        const int q0 = (bn + warp_n) & 127;
        const float hb = __ldg(&h_bias[h]);
        float* __restrict__ C = Cp + ((size_t)(z * HO_ + h) * NV_) * NQ_;
#pragma unroll
        for (int nf = 0; nf < 8; ++nf) {
            const int qn = q0 + nf * 8 + 2 * tig;
#pragma unroll
            for (int mf = 0; mf < 4; ++mf) {
                const int vm = bm + warp_m + mf * 16 + group;
                float2 lo, hi;
                lo.x = acc[mf][nf][0] + hb;
                lo.y = acc[mf][nf][1] + hb;
                hi.x = acc[mf][nf][2] + hb;
                hi.y = acc[mf][nf][3] + hb;
                *(float2*)(C + (size_t)vm * NQ_ + qn)       = lo;
                *(float2*)(C + (size_t)(vm + 8) * NQ_ + qn) = hi;
            }
        }
    }
}

// ---------------------------------------------------------------------------
// inputs: v, q, Wv, bv, Wq, bq, h_mat, h_bias ; output fp32 (32,8,512,128)
// ---------------------------------------------------------------------------
static inline unsigned bgrid(size_t nblk) { return (unsigned)((nblk + 255) / 256); }

extern "C" void kernel_launch(void* const* d_in, const int* in_sizes, int n_in,
                              void* d_out, int out_size)
{
    const float* v      = (const float*)d_in[0];
    const float* q      = (const float*)d_in[1];
    const float* Wv     = (const float*)d_in[2];
    const float* bv     = (const float*)d_in[3];
    const float* Wq     = (const float*)d_in[4];
    const float* bq     = (const float*)d_in[5];
    const float* h_mat  = (const float*)d_in[6];
    const float* h_bias = (const float*)d_in[7];
    float* out = (float*)d_out;

    cudaFuncSetAttribute(gemm_mma, cudaFuncAttributeMaxDynamicSharedMemorySize,
                         SMEM_BYTES);

    const size_t blk_v  = (size_t)B_ * NV_ * VD_ / 32;
    const size_t blk_q  = (size_t)B_ * NQ_ * QD_ / 32;
    const size_t blk_wv = (size_t)HK_ * VD_ / 32;
    const size_t blk_wq = (size_t)HK_ * QD_ / 32;
    const size_t blk_gv = (size_t)B_ * NV_ * HK_ / 32;
    const size_t blk_qh = (size_t)B_ * HO_ * NQ_ * (HK_ / 32);

    perm_cvt<<<bgrid(blk_v),  256>>>(v,  0, blk_v);       // 0
    perm_cvt<<<bgrid(blk_wv), 256>>>(Wv, 2, blk_wv);      // 1
    perm_cvt<<<bgrid(blk_q),  256>>>(q,  1, blk_q);       // 2
    perm_cvt<<<bgrid(blk_wq), 256>>>(Wq, 3, blk_wq);      // 3
    // G2: q-proj -> g_q  M=4096 N=1536 K=1024
    gemm_mma<<<dim3((B_ * NQ_) / BM, HK_ / BN, 1), 256, SMEM_BYTES>>>(
        bq, nullptr, nullptr, HK_, QD_, 1);               // 4
    // G1: v-proj -> g_v  M=16384 N=1536 K=2048           // 5
    gemm_mma<<<dim3((B_ * NV_) / BM, HK_ / BN, 1), 256, SMEM_BYTES>>>(
        bv, nullptr, nullptr, HK_, VD_, 0);
    qh_cvt<<<bgrid(blk_qh), 256>>>(h_mat);                // 6
    perm_cvt<<<bgrid(blk_gv), 256>>>(nullptr, 4, blk_gv); // 7
    // G3: bilinear -> out  per z: M=512 N=1024(8h x 128q) K=1536
    gemm_mma<<<dim3(NV_ / BM, (HO_ * NQ_) / BN, B_), 256, SMEM_BYTES>>>(
        nullptr, h_bias, out, HO_ * NQ_, HK_, 2);         // 8
}

// round 13
// speedup vs baseline: 1.0446x; 1.0446x over previous
#include <cuda_runtime.h>
#include <cstdint>

// ---------------------------------------------------------------------------
// BCNet, tf32 mma.sync. k-perm = 8x4 transpose within each 32-float block
// (k = 4*j + t <-> kappa = 8*t + j) on both operands -> LDS.128 fragments.
// R12: recombination of measured-best parts:
//   - GEMM: R8 config verbatim (128x128 tile, 8 warps of 64x32, 3-stage
//     cp.async, prefetch-before-compute, two barriers, mf-paired fragments)
//   - pre-passes: R10 fast vectorized register-transpose perm_cvt / qh_cvt
// ---------------------------------------------------------------------------

#define B_   32
#define NV_  512
#define NQ_  128
#define VD_  2048
#define QD_  1024
#define HK_  1536
#define HO_  8

__device__ float g_at [(size_t)B_ * NV_ * VD_];      // perm/cvt v      134MB
__device__ float g_qt [(size_t)B_ * NQ_ * QD_];      // perm/cvt q       17MB
__device__ float g_wvt[(size_t)HK_ * VD_];           // perm/cvt Wv      13MB
__device__ float g_wqt[(size_t)HK_ * QD_];           // perm/cvt Wq       6MB
__device__ float g_v  [(size_t)B_ * NV_ * HK_];      // G1 out plain    100MB
__device__ float g_vtp[(size_t)B_ * NV_ * HK_];      // perm/cvt g_v    100MB
__device__ float g_q  [(size_t)B_ * NQ_ * HK_];      // G2 out plain     25MB
__device__ float g_qh [(size_t)B_ * HO_ * NQ_ * HK_];// perm(q*hm)      201MB

#define BM 128
#define BN 128
#define KT 32
#define PROW 144                      // smem row stride bytes (36 floats)
#define A_BYTES (BM * PROW)           // 18432
#define STAGE_BYTES (2 * A_BYTES)     // 36864 (A then B)
#define NSTAGE 3
#define SMEM_BYTES (NSTAGE * STAGE_BYTES)   // 110592

__device__ __forceinline__ uint32_t rna(float x) {
    uint32_t y; asm("cvt.rna.tf32.f32 %0, %1;" : "=r"(y) : "f"(x)); return y;
}
__device__ __forceinline__ uint32_t smem_u32(const void* p) {
    uint32_t a;
    asm("{ .reg .u64 t; cvta.to.shared.u64 t, %1; cvt.u32.u64 %0, t; }"
        : "=r"(a) : "l"(p));
    return a;
}
__device__ __forceinline__ void cpa16(uint32_t dst, const void* src) {
    asm volatile("cp.async.cg.shared.global [%0], [%1], 16;"
                 :: "r"(dst), "l"(src) : "memory");
}
__device__ __forceinline__ void cpa_commit() {
    asm volatile("cp.async.commit_group;" ::: "memory");
}
__device__ __forceinline__ void cpa_wait1() {
    asm volatile("cp.async.wait_group 1;" ::: "memory");
}
__device__ __forceinline__ void mma8(float& d0, float& d1, float& d2, float& d3,
                                     uint32_t a0, uint32_t a1, uint32_t a2, uint32_t a3,
                                     uint32_t b0, uint32_t b1) {
    asm volatile(
        "mma.sync.aligned.m16n8k8.row.col.f32.tf32.tf32.f32 "
        "{%0,%1,%2,%3}, {%4,%5,%6,%7}, {%8,%9}, {%0,%1,%2,%3};"
        : "+f"(d0), "+f"(d1), "+f"(d2), "+f"(d3)
        : "r"(a0), "r"(a1), "r"(a2), "r"(a3), "r"(b0), "r"(b1));
}

// --------------- pre-pass: vectorized 8x4 block transpose + cvt -----------
// dsel: 0->g_at, 1->g_qt, 2->g_wvt, 3->g_wqt, 4->g_vtp(src=g_v)
__global__ void __launch_bounds__(256)
perm_cvt(const float* __restrict__ src_in, int dsel, size_t nblk)
{
    const size_t idx = (size_t)blockIdx.x * blockDim.x + threadIdx.x;
    if (idx >= nblk) return;
    const float* __restrict__ src = (dsel == 4) ? g_v : src_in;
    float* __restrict__ dstf =
        (dsel == 0) ? g_at : (dsel == 1) ? g_qt :
        (dsel == 2) ? g_wvt : (dsel == 3) ? g_wqt : g_vtp;

    const float4* __restrict__ s = (const float4*)src + idx * 8;
    float rr[32];
#pragma unroll
    for (int j = 0; j < 8; ++j) {
        const float4 t4 = s[j];
        rr[4 * j + 0] = t4.x; rr[4 * j + 1] = t4.y;
        rr[4 * j + 2] = t4.z; rr[4 * j + 3] = t4.w;
    }
    uint4* __restrict__ d = (uint4*)dstf + idx * 8;
#pragma unroll
    for (int t = 0; t < 4; ++t) {
#pragma unroll
        for (int b = 0; b < 2; ++b) {
            uint4 o;
            o.x = rna(rr[(4 * b + 0) * 4 + t]);
            o.y = rna(rr[(4 * b + 1) * 4 + t]);
            o.z = rna(rr[(4 * b + 2) * 4 + t]);
            o.w = rna(rr[(4 * b + 3) * 4 + t]);
            d[t * 2 + b] = o;
        }
    }
}

// ---- qh pass: g_qh[(z*8+h)*128+q] = perm(rna(g_q[z*128+q] * h_mat[h])) ----
__global__ void __launch_bounds__(256)
qh_cvt(const float* __restrict__ h_mat)
{
    const size_t nblk = (size_t)B_ * HO_ * NQ_ * (HK_ / 32);
    const size_t idx = (size_t)blockIdx.x * blockDim.x + threadIdx.x;
    if (idx >= nblk) return;
    const int BPR = HK_ / 32;
    const size_t row = idx / BPR;
    const int blk = (int)(idx % BPR);
    const int q = (int)(row & 127);
    const int h = (int)((row >> 7) & 7);
    const int z = (int)(row >> 10);

    const float4* __restrict__ s = (const float4*)
        (g_q + ((size_t)z * NQ_ + q) * HK_) + blk * 8;
    const float4* __restrict__ hm = (const float4*)
        (h_mat + (size_t)h * HK_) + blk * 8;

    float rr[32];
#pragma unroll
    for (int j = 0; j < 8; ++j) {
        const float4 a = s[j];
        const float4 m = hm[j];
        rr[4 * j + 0] = a.x * m.x; rr[4 * j + 1] = a.y * m.y;
        rr[4 * j + 2] = a.z * m.z; rr[4 * j + 3] = a.w * m.w;
    }
    uint4* __restrict__ d = (uint4*)(g_qh + row * HK_) + blk * 8;
#pragma unroll
    for (int t = 0; t < 4; ++t) {
#pragma unroll
        for (int b = 0; b < 2; ++b) {
            uint4 o;
            o.x = rna(rr[(4 * b + 0) * 4 + t]);
            o.y = rna(rr[(4 * b + 1) * 4 + t]);
            o.z = rna(rr[(4 * b + 2) * 4 + t]);
            o.w = rna(rr[(4 * b + 3) * 4 + t]);
            d[t * 2 + b] = o;
        }
    }
}

// ------------------------------ GEMM kernel (R8 config) -------------------
// sel0: A=g_at, B=g_wvt -> g_v plain (relu+bias)
// sel1: A=g_qt, B=g_wqt -> g_q plain (relu+bias)
// sel2: A=g_vtp[z], B=g_qh[z] -> Cp (+h_bias[h]), h=blockIdx.y
__global__ void __launch_bounds__(256)
gemm_mma(const float* __restrict__ bias, const float* __restrict__ h_bias,
         float* __restrict__ Cp, int Ntot, int K, int sel)
{
    extern __shared__ char smem[];
    const uint32_t smb = smem_u32(smem);

    const int tid   = threadIdx.x;
    const int wid   = tid >> 5;
    const int lane  = tid & 31;
    const int group = lane >> 2;
    const int tig   = lane & 3;
    const int warp_m = (wid & 1) * 64;
    const int warp_n = (wid >> 1) * 32;

    const int bm = blockIdx.x * BM;
    const int bn = blockIdx.y * BN;
    const int z  = blockIdx.z;
    const int mode = (sel == 2);

    const float* __restrict__ Abase =
        (sel == 0) ? g_at : (sel == 1) ? g_qt : g_vtp;
    const float* __restrict__ Bbase =
        (sel == 0) ? g_wvt : (sel == 1) ? g_wqt : g_qh;

    const float* __restrict__ Ag = Abase +
        ((size_t)(mode ? z * NV_ : 0) + bm) * K;
    const float* __restrict__ Bg = Bbase +
        ((size_t)(mode ? z * (HO_ * NQ_) : 0) + bn) * K;

    const int r0 = tid >> 3;
    const int s4 = (tid & 7) * 4;
    const uint32_t stg_off = (uint32_t)(r0 * PROW + s4 * 4);

    float acc[4][4][4];
#pragma unroll
    for (int i = 0; i < 4; ++i)
#pragma unroll
        for (int j = 0; j < 4; ++j)
#pragma unroll
            for (int l = 0; l < 4; ++l) acc[i][j][l] = 0.f;

    const int NC = K / KT;

    // prologue: stages 0 and 1
#pragma unroll
    for (int s = 0; s < 2; ++s) {
        const uint32_t sb = smb + s * STAGE_BYTES;
        const int k0 = s * KT;
#pragma unroll
        for (int i = 0; i < 4; ++i) {
            const int r = r0 + 32 * i;
            cpa16(sb + stg_off + i * 32 * PROW,
                  Ag + (size_t)r * K + k0 + s4);
            cpa16(sb + A_BYTES + stg_off + i * 32 * PROW,
                  Bg + (size_t)r * K + k0 + s4);
        }
        cpa_commit();
    }

    const int tb = tig * 32;

    for (int c = 0; c < NC; ++c) {
        cpa_wait1();
        __syncthreads();

        if (c + 2 < NC) {
            const uint32_t sb = smb + ((c + 2) % NSTAGE) * STAGE_BYTES;
            const int k0 = (c + 2) * KT;
#pragma unroll
            for (int i = 0; i < 4; ++i) {
                const int r = r0 + 32 * i;
                cpa16(sb + stg_off + i * 32 * PROW,
                      Ag + (size_t)r * K + k0 + s4);
                cpa16(sb + A_BYTES + stg_off + i * 32 * PROW,
                      Bg + (size_t)r * K + k0 + s4);
            }
        }
        cpa_commit();

        const char* sa = smem + (c % NSTAGE) * STAGE_BYTES;
        const char* sbuf = sa + A_BYTES;
#pragma unroll
        for (int hf = 0; hf < 2; ++hf) {          // kk pairs {0,1},{2,3}
            const int hb = hf * 16;
#pragma unroll
            for (int mp = 0; mp < 2; ++mp) {      // mf pairs: low pressure
                uint4 aL0, aH0, aL1, aH1;
                {
                    const int m0 = warp_m + (mp * 2 + 0) * 16 + group;
                    const int m1 = warp_m + (mp * 2 + 1) * 16 + group;
                    aL0 = *(const uint4*)(sa + m0 * PROW + tb + hb);
                    aH0 = *(const uint4*)(sa + (m0 + 8) * PROW + tb + hb);
                    aL1 = *(const uint4*)(sa + m1 * PROW + tb + hb);
                    aH1 = *(const uint4*)(sa + (m1 + 8) * PROW + tb + hb);
                }
#pragma unroll
                for (int nf = 0; nf < 4; ++nf) {
                    const uint4 bv = *(const uint4*)(sbuf +
                        (warp_n + nf * 8 + group) * PROW + tb + hb);
                    const int mf0 = mp * 2, mf1 = mp * 2 + 1;
                    mma8(acc[mf0][nf][0], acc[mf0][nf][1],
                         acc[mf0][nf][2], acc[mf0][nf][3],
                         aL0.x, aH0.x, aL0.y, aH0.y, bv.x, bv.y);
                    mma8(acc[mf0][nf][0], acc[mf0][nf][1],
                         acc[mf0][nf][2], acc[mf0][nf][3],
                         aL0.z, aH0.z, aL0.w, aH0.w, bv.z, bv.w);
                    mma8(acc[mf1][nf][0], acc[mf1][nf][1],
                         acc[mf1][nf][2], acc[mf1][nf][3],
                         aL1.x, aH1.x, aL1.y, aH1.y, bv.x, bv.y);
                    mma8(acc[mf1][nf][0], acc[mf1][nf][1],
                         acc[mf1][nf][2], acc[mf1][nf][3],
                         aL1.z, aH1.z, aL1.w, aH1.w, bv.z, bv.w);
                }
            }
        }
        __syncthreads();
    }

    // ---------------------------- epilogue --------------------------------
    if (!mode) {
        float* __restrict__ C = (sel == 0) ? g_v : g_q;
#pragma unroll
        for (int nf = 0; nf < 4; ++nf) {
            const int gn = bn + warp_n + nf * 8 + 2 * tig;
            const float b0 = __ldg(&bias[gn]);
            const float b1 = __ldg(&bias[gn + 1]);
#pragma unroll
            for (int mf = 0; mf < 4; ++mf) {
                const int gm = bm + warp_m + mf * 16 + group;
                float2 lo, hi;
                lo.x = fmaxf(acc[mf][nf][0] + b0, 0.f);
                lo.y = fmaxf(acc[mf][nf][1] + b1, 0.f);
                hi.x = fmaxf(acc[mf][nf][2] + b0, 0.f);
                hi.y = fmaxf(acc[mf][nf][3] + b1, 0.f);
                *(float2*)(C + (size_t)gm * Ntot + gn)       = lo;
                *(float2*)(C + (size_t)(gm + 8) * Ntot + gn) = hi;
            }
        }
    } else {
        const int h = blockIdx.y;
        const float hb = __ldg(&h_bias[h]);
        float* __restrict__ C = Cp + ((size_t)(z * HO_ + h) * NV_) * NQ_;
#pragma unroll
        for (int nf = 0; nf < 4; ++nf) {
            const int qn = warp_n + nf * 8 + 2 * tig;
#pragma unroll
            for (int mf = 0; mf < 4; ++mf) {
                const int vm = bm + warp_m + mf * 16 + group;
                float2 lo, hi;
                lo.x = acc[mf][nf][0] + hb;
                lo.y = acc[mf][nf][1] + hb;
                hi.x = acc[mf][nf][2] + hb;
                hi.y = acc[mf][nf][3] + hb;
                *(float2*)(C + (size_t)vm * NQ_ + qn)       = lo;
                *(float2*)(C + (size_t)(vm + 8) * NQ_ + qn) = hi;
            }
        }
    }
}

// ---------------------------------------------------------------------------
// inputs: v, q, Wv, bv, Wq, bq, h_mat, h_bias ; output fp32 (32,8,512,128)
// ---------------------------------------------------------------------------
static inline unsigned bgrid(size_t nblk) { return (unsigned)((nblk + 255) / 256); }

extern "C" void kernel_launch(void* const* d_in, const int* in_sizes, int n_in,
                              void* d_out, int out_size)
{
    const float* v      = (const float*)d_in[0];
    const float* q      = (const float*)d_in[1];
    const float* Wv     = (const float*)d_in[2];
    const float* bv     = (const float*)d_in[3];
    const float* Wq     = (const float*)d_in[4];
    const float* bq     = (const float*)d_in[5];
    const float* h_mat  = (const float*)d_in[6];
    const float* h_bias = (const float*)d_in[7];
    float* out = (float*)d_out;

    cudaFuncSetAttribute(gemm_mma, cudaFuncAttributeMaxDynamicSharedMemorySize,
                         SMEM_BYTES);

    const size_t blk_v  = (size_t)B_ * NV_ * VD_ / 32;
    const size_t blk_q  = (size_t)B_ * NQ_ * QD_ / 32;
    const size_t blk_wv = (size_t)HK_ * VD_ / 32;
    const size_t blk_wq = (size_t)HK_ * QD_ / 32;
    const size_t blk_gv = (size_t)B_ * NV_ * HK_ / 32;
    const size_t blk_qh = (size_t)B_ * HO_ * NQ_ * (HK_ / 32);

    perm_cvt<<<bgrid(blk_v),  256>>>(v,  0, blk_v);       // 0
    perm_cvt<<<bgrid(blk_wv), 256>>>(Wv, 2, blk_wv);      // 1
    perm_cvt<<<bgrid(blk_q),  256>>>(q,  1, blk_q);       // 2
    perm_cvt<<<bgrid(blk_wq), 256>>>(Wq, 3, blk_wq);      // 3
    // G2: q-proj -> g_q  M=4096 N=1536 K=1024
    gemm_mma<<<dim3((B_ * NQ_) / BM, HK_ / BN, 1), 256, SMEM_BYTES>>>(
        bq, nullptr, nullptr, HK_, QD_, 1);               // 4
    // G1: v-proj -> g_v  M=16384 N=1536 K=2048           // 5
    gemm_mma<<<dim3((B_ * NV_) / BM, HK_ / BN, 1), 256, SMEM_BYTES>>>(
        bv, nullptr, nullptr, HK_, VD_, 0);
    qh_cvt<<<bgrid(blk_qh), 256>>>(h_mat);                // 6
    perm_cvt<<<bgrid(blk_gv), 256>>>(nullptr, 4, blk_gv); // 7
    // G3: bilinear -> out  per z: M=512 N=1024(8h x 128q) K=1536
    gemm_mma<<<dim3(NV_ / BM, (HO_ * NQ_) / BN, B_), 256, SMEM_BYTES>>>(
        nullptr, h_bias, out, HO_ * NQ_, HK_, 2);         // 8
}

// round 14
// speedup vs baseline: 1.3833x; 1.3242x over previous
#include <cuda_runtime.h>
#include <cstdint>

// ---------------------------------------------------------------------------
// BCNet, tf32 mma.sync. k-perm = 8x4 transpose within each 32-float block
// (k = 4*j + t <-> kappa = 8*t + j) on both operands -> LDS.128 fragments.
// R13: R12 with PROW 144 -> 128 + XOR segment swizzle (seg ^= row&7).
//      Stage 36.9KB -> 32KB, smem/CTA 110.6KB -> 96KB => 2 CTAs/SM.
// ---------------------------------------------------------------------------

#define B_   32
#define NV_  512
#define NQ_  128
#define VD_  2048
#define QD_  1024
#define HK_  1536
#define HO_  8

__device__ float g_at [(size_t)B_ * NV_ * VD_];      // perm/cvt v      134MB
__device__ float g_qt [(size_t)B_ * NQ_ * QD_];      // perm/cvt q       17MB
__device__ float g_wvt[(size_t)HK_ * VD_];           // perm/cvt Wv      13MB
__device__ float g_wqt[(size_t)HK_ * QD_];           // perm/cvt Wq       6MB
__device__ float g_v  [(size_t)B_ * NV_ * HK_];      // G1 out plain    100MB
__device__ float g_vtp[(size_t)B_ * NV_ * HK_];      // perm/cvt g_v    100MB
__device__ float g_q  [(size_t)B_ * NQ_ * HK_];      // G2 out plain     25MB
__device__ float g_qh [(size_t)B_ * HO_ * NQ_ * HK_];// perm(q*hm)      201MB

#define BM 128
#define BN 128
#define KT 32
#define PROW 128                      // smem row stride bytes (XOR swizzle)
#define A_BYTES (BM * PROW)           // 16384
#define STAGE_BYTES (2 * A_BYTES)     // 32768 (A then B)
#define NSTAGE 3
#define SMEM_BYTES (NSTAGE * STAGE_BYTES)   // 98304 -> 2 CTAs/SM

__device__ __forceinline__ uint32_t rna(float x) {
    uint32_t y; asm("cvt.rna.tf32.f32 %0, %1;" : "=r"(y) : "f"(x)); return y;
}
__device__ __forceinline__ uint32_t smem_u32(const void* p) {
    uint32_t a;
    asm("{ .reg .u64 t; cvta.to.shared.u64 t, %1; cvt.u32.u64 %0, t; }"
        : "=r"(a) : "l"(p));
    return a;
}
__device__ __forceinline__ void cpa16(uint32_t dst, const void* src) {
    asm volatile("cp.async.cg.shared.global [%0], [%1], 16;"
                 :: "r"(dst), "l"(src) : "memory");
}
__device__ __forceinline__ void cpa_commit() {
    asm volatile("cp.async.commit_group;" ::: "memory");
}
__device__ __forceinline__ void cpa_wait1() {
    asm volatile("cp.async.wait_group 1;" ::: "memory");
}
__device__ __forceinline__ void mma8(float& d0, float& d1, float& d2, float& d3,
                                     uint32_t a0, uint32_t a1, uint32_t a2, uint32_t a3,
                                     uint32_t b0, uint32_t b1) {
    asm volatile(
        "mma.sync.aligned.m16n8k8.row.col.f32.tf32.tf32.f32 "
        "{%0,%1,%2,%3}, {%4,%5,%6,%7}, {%8,%9}, {%0,%1,%2,%3};"
        : "+f"(d0), "+f"(d1), "+f"(d2), "+f"(d3)
        : "r"(a0), "r"(a1), "r"(a2), "r"(a3), "r"(b0), "r"(b1));
}

// --------------- pre-pass: vectorized 8x4 block transpose + cvt -----------
// dsel: 0->g_at, 1->g_qt, 2->g_wvt, 3->g_wqt, 4->g_vtp(src=g_v)
__global__ void __launch_bounds__(256)
perm_cvt(const float* __restrict__ src_in, int dsel, size_t nblk)
{
    const size_t idx = (size_t)blockIdx.x * blockDim.x + threadIdx.x;
    if (idx >= nblk) return;
    const float* __restrict__ src = (dsel == 4) ? g_v : src_in;
    float* __restrict__ dstf =
        (dsel == 0) ? g_at : (dsel == 1) ? g_qt :
        (dsel == 2) ? g_wvt : (dsel == 3) ? g_wqt : g_vtp;

    const float4* __restrict__ s = (const float4*)src + idx * 8;
    float rr[32];
#pragma unroll
    for (int j = 0; j < 8; ++j) {
        const float4 t4 = s[j];
        rr[4 * j + 0] = t4.x; rr[4 * j + 1] = t4.y;
        rr[4 * j + 2] = t4.z; rr[4 * j + 3] = t4.w;
    }
    uint4* __restrict__ d = (uint4*)dstf + idx * 8;
#pragma unroll
    for (int t = 0; t < 4; ++t) {
#pragma unroll
        for (int b = 0; b < 2; ++b) {
            uint4 o;
            o.x = rna(rr[(4 * b + 0) * 4 + t]);
            o.y = rna(rr[(4 * b + 1) * 4 + t]);
            o.z = rna(rr[(4 * b + 2) * 4 + t]);
            o.w = rna(rr[(4 * b + 3) * 4 + t]);
            d[t * 2 + b] = o;
        }
    }
}

// ---- qh pass: g_qh[(z*8+h)*128+q] = perm(rna(g_q[z*128+q] * h_mat[h])) ----
__global__ void __launch_bounds__(256)
qh_cvt(const float* __restrict__ h_mat)
{
    const size_t nblk = (size_t)B_ * HO_ * NQ_ * (HK_ / 32);
    const size_t idx = (size_t)blockIdx.x * blockDim.x + threadIdx.x;
    if (idx >= nblk) return;
    const int BPR = HK_ / 32;
    const size_t row = idx / BPR;
    const int blk = (int)(idx % BPR);
    const int q = (int)(row & 127);
    const int h = (int)((row >> 7) & 7);
    const int z = (int)(row >> 10);

    const float4* __restrict__ s = (const float4*)
        (g_q + ((size_t)z * NQ_ + q) * HK_) + blk * 8;
    const float4* __restrict__ hm = (const float4*)
        (h_mat + (size_t)h * HK_) + blk * 8;

    float rr[32];
#pragma unroll
    for (int j = 0; j < 8; ++j) {
        const float4 a = s[j];
        const float4 m = hm[j];
        rr[4 * j + 0] = a.x * m.x; rr[4 * j + 1] = a.y * m.y;
        rr[4 * j + 2] = a.z * m.z; rr[4 * j + 3] = a.w * m.w;
    }
    uint4* __restrict__ d = (uint4*)(g_qh + row * HK_) + blk * 8;
#pragma unroll
    for (int t = 0; t < 4; ++t) {
#pragma unroll
        for (int b = 0; b < 2; ++b) {
            uint4 o;
            o.x = rna(rr[(4 * b + 0) * 4 + t]);
            o.y = rna(rr[(4 * b + 1) * 4 + t]);
            o.z = rna(rr[(4 * b + 2) * 4 + t]);
            o.w = rna(rr[(4 * b + 3) * 4 + t]);
            d[t * 2 + b] = o;
        }
    }
}

// ------------------------------ GEMM kernel -------------------------------
// smem layout: row r (128B) holds 8 16B segments, stored at seg^(r&7).
// sel0: A=g_at, B=g_wvt -> g_v plain (relu+bias)
// sel1: A=g_qt, B=g_wqt -> g_q plain (relu+bias)
// sel2: A=g_vtp[z], B=g_qh[z] -> Cp (+h_bias[h]), h=blockIdx.y
__global__ void __launch_bounds__(256)
gemm_mma(const float* __restrict__ bias, const float* __restrict__ h_bias,
         float* __restrict__ Cp, int Ntot, int K, int sel)
{
    extern __shared__ char smem[];
    const uint32_t smb = smem_u32(smem);

    const int tid   = threadIdx.x;
    const int wid   = tid >> 5;
    const int lane  = tid & 31;
    const int group = lane >> 2;
    const int tig   = lane & 3;
    const int warp_m = (wid & 1) * 64;
    const int warp_n = (wid >> 1) * 32;

    const int bm = blockIdx.x * BM;
    const int bn = blockIdx.y * BN;
    const int z  = blockIdx.z;
    const int mode = (sel == 2);

    const float* __restrict__ Abase =
        (sel == 0) ? g_at : (sel == 1) ? g_qt : g_vtp;
    const float* __restrict__ Bbase =
        (sel == 0) ? g_wvt : (sel == 1) ? g_wqt : g_qh;

    const float* __restrict__ Ag = Abase +
        ((size_t)(mode ? z * NV_ : 0) + bm) * K;
    const float* __restrict__ Bg = Bbase +
        ((size_t)(mode ? z * (HO_ * NQ_) : 0) + bn) * K;

    const int r0 = tid >> 3;                  // staging row 0..31
    const int sseg = tid & 7;                 // staging segment 0..7
    const int s4 = sseg * 4;                  // segment offset (floats)
    // swizzled staging offset: row*128 + (seg ^ (row&7))*16
    const uint32_t stg_off =
        (uint32_t)(r0 * PROW + ((sseg ^ (r0 & 7)) << 4));

    float acc[4][4][4];
#pragma unroll
    for (int i = 0; i < 4; ++i)
#pragma unroll
        for (int j = 0; j < 4; ++j)
#pragma unroll
            for (int l = 0; l < 4; ++l) acc[i][j][l] = 0.f;

    const int NC = K / KT;

    // prologue: stages 0 and 1
#pragma unroll
    for (int s = 0; s < 2; ++s) {
        const uint32_t sb = smb + s * STAGE_BYTES;
        const int k0 = s * KT;
#pragma unroll
        for (int i = 0; i < 4; ++i) {
            const int r = r0 + 32 * i;        // r&7 == r0&7
            cpa16(sb + stg_off + i * 32 * PROW,
                  Ag + (size_t)r * K + k0 + s4);
            cpa16(sb + A_BYTES + stg_off + i * 32 * PROW,
                  Bg + (size_t)r * K + k0 + s4);
        }
        cpa_commit();
    }

    for (int c = 0; c < NC; ++c) {
        cpa_wait1();
        __syncthreads();

        if (c + 2 < NC) {
            const uint32_t sb = smb + ((c + 2) % NSTAGE) * STAGE_BYTES;
            const int k0 = (c + 2) * KT;
#pragma unroll
            for (int i = 0; i < 4; ++i) {
                const int r = r0 + 32 * i;
                cpa16(sb + stg_off + i * 32 * PROW,
                      Ag + (size_t)r * K + k0 + s4);
                cpa16(sb + A_BYTES + stg_off + i * 32 * PROW,
                      Bg + (size_t)r * K + k0 + s4);
            }
        }
        cpa_commit();

        const char* sa = smem + (c % NSTAGE) * STAGE_BYTES;
        const char* sbuf = sa + A_BYTES;
#pragma unroll
        for (int hf = 0; hf < 2; ++hf) {          // kk pairs {0,1},{2,3}
            // fragment segment index = tig*2 + hf, swizzled by row&7==group
            const int fsw = ((tig * 2 + hf) ^ group) << 4;
#pragma unroll
            for (int mp = 0; mp < 2; ++mp) {      // mf pairs: low pressure
                uint4 aL0, aH0, aL1, aH1;
                {
                    const int m0 = warp_m + (mp * 2 + 0) * 16 + group;
                    const int m1 = warp_m + (mp * 2 + 1) * 16 + group;
                    aL0 = *(const uint4*)(sa + m0 * PROW + fsw);
                    aH0 = *(const uint4*)(sa + (m0 + 8) * PROW + fsw);
                    aL1 = *(const uint4*)(sa + m1 * PROW + fsw);
                    aH1 = *(const uint4*)(sa + (m1 + 8) * PROW + fsw);
                }
#pragma unroll
                for (int nf = 0; nf < 4; ++nf) {
                    const uint4 bv = *(const uint4*)(sbuf +
                        (warp_n + nf * 8 + group) * PROW + fsw);
                    const int mf0 = mp * 2, mf1 = mp * 2 + 1;
                    mma8(acc[mf0][nf][0], acc[mf0][nf][1],
                         acc[mf0][nf][2], acc[mf0][nf][3],
                         aL0.x, aH0.x, aL0.y, aH0.y, bv.x, bv.y);
                    mma8(acc[mf0][nf][0], acc[mf0][nf][1],
                         acc[mf0][nf][2], acc[mf0][nf][3],
                         aL0.z, aH0.z, aL0.w, aH0.w, bv.z, bv.w);
                    mma8(acc[mf1][nf][0], acc[mf1][nf][1],
                         acc[mf1][nf][2], acc[mf1][nf][3],
                         aL1.x, aH1.x, aL1.y, aH1.y, bv.x, bv.y);
                    mma8(acc[mf1][nf][0], acc[mf1][nf][1],
                         acc[mf1][nf][2], acc[mf1][nf][3],
                         aL1.z, aH1.z, aL1.w, aH1.w, bv.z, bv.w);
                }
            }
        }
        __syncthreads();
    }

    // ---------------------------- epilogue --------------------------------
    if (!mode) {
        float* __restrict__ C = (sel == 0) ? g_v : g_q;
#pragma unroll
        for (int nf = 0; nf < 4; ++nf) {
            const int gn = bn + warp_n + nf * 8 + 2 * tig;
            const float b0 = __ldg(&bias[gn]);
            const float b1 = __ldg(&bias[gn + 1]);
#pragma unroll
            for (int mf = 0; mf < 4; ++mf) {
                const int gm = bm + warp_m + mf * 16 + group;
                float2 lo, hi;
                lo.x = fmaxf(acc[mf][nf][0] + b0, 0.f);
                lo.y = fmaxf(acc[mf][nf][1] + b1, 0.f);
                hi.x = fmaxf(acc[mf][nf][2] + b0, 0.f);
                hi.y = fmaxf(acc[mf][nf][3] + b1, 0.f);
                *(float2*)(C + (size_t)gm * Ntot + gn)       = lo;
                *(float2*)(C + (size_t)(gm + 8) * Ntot + gn) = hi;
            }
        }
    } else {
        const int h = blockIdx.y;
        const float hb = __ldg(&h_bias[h]);
        float* __restrict__ C = Cp + ((size_t)(z * HO_ + h) * NV_) * NQ_;
#pragma unroll
        for (int nf = 0; nf < 4; ++nf) {
            const int qn = warp_n + nf * 8 + 2 * tig;
#pragma unroll
            for (int mf = 0; mf < 4; ++mf) {
                const int vm = bm + warp_m + mf * 16 + group;
                float2 lo, hi;
                lo.x = acc[mf][nf][0] + hb;
                lo.y = acc[mf][nf][1] + hb;
                hi.x = acc[mf][nf][2] + hb;
                hi.y = acc[mf][nf][3] + hb;
                *(float2*)(C + (size_t)vm * NQ_ + qn)       = lo;
                *(float2*)(C + (size_t)(vm + 8) * NQ_ + qn) = hi;
            }
        }
    }
}

// ---------------------------------------------------------------------------
// inputs: v, q, Wv, bv, Wq, bq, h_mat, h_bias ; output fp32 (32,8,512,128)
// ---------------------------------------------------------------------------
static inline unsigned bgrid(size_t nblk) { return (unsigned)((nblk + 255) / 256); }

extern "C" void kernel_launch(void* const* d_in, const int* in_sizes, int n_in,
                              void* d_out, int out_size)
{
    const float* v      = (const float*)d_in[0];
    const float* q      = (const float*)d_in[1];
    const float* Wv     = (const float*)d_in[2];
    const float* bv     = (const float*)d_in[3];
    const float* Wq     = (const float*)d_in[4];
    const float* bq     = (const float*)d_in[5];
    const float* h_mat  = (const float*)d_in[6];
    const float* h_bias = (const float*)d_in[7];
    float* out = (float*)d_out;

    cudaFuncSetAttribute(gemm_mma, cudaFuncAttributeMaxDynamicSharedMemorySize,
                         SMEM_BYTES);

    const size_t blk_v  = (size_t)B_ * NV_ * VD_ / 32;
    const size_t blk_q  = (size_t)B_ * NQ_ * QD_ / 32;
    const size_t blk_wv = (size_t)HK_ * VD_ / 32;
    const size_t blk_wq = (size_t)HK_ * QD_ / 32;
    const size_t blk_gv = (size_t)B_ * NV_ * HK_ / 32;
    const size_t blk_qh = (size_t)B_ * HO_ * NQ_ * (HK_ / 32);

    perm_cvt<<<bgrid(blk_v),  256>>>(v,  0, blk_v);       // 0
    perm_cvt<<<bgrid(blk_wv), 256>>>(Wv, 2, blk_wv);      // 1
    perm_cvt<<<bgrid(blk_q),  256>>>(q,  1, blk_q);       // 2
    perm_cvt<<<bgrid(blk_wq), 256>>>(Wq, 3, blk_wq);      // 3
    // G2: q-proj -> g_q  M=4096 N=1536 K=1024
    gemm_mma<<<dim3((B_ * NQ_) / BM, HK_ / BN, 1), 256, SMEM_BYTES>>>(
        bq, nullptr, nullptr, HK_, QD_, 1);               // 4
    // G1: v-proj -> g_v  M=16384 N=1536 K=2048           // 5
    gemm_mma<<<dim3((B_ * NV_) / BM, HK_ / BN, 1), 256, SMEM_BYTES>>>(
        bv, nullptr, nullptr, HK_, VD_, 0);
    qh_cvt<<<bgrid(blk_qh), 256>>>(h_mat);                // 6
    perm_cvt<<<bgrid(blk_gv), 256>>>(nullptr, 4, blk_gv); // 7
    // G3: bilinear -> out  per z: M=512 N=1024(8h x 128q) K=1536
    gemm_mma<<<dim3(NV_ / BM, (HO_ * NQ_) / BN, B_), 256, SMEM_BYTES>>>(
        nullptr, h_bias, out, HO_ * NQ_, HK_, 2);         // 8
}

// round 15
// speedup vs baseline: 1.4125x; 1.0211x over previous
#include <cuda_runtime.h>
#include <cstdint>

// ---------------------------------------------------------------------------
// BCNet, tf32 mma.sync. k-perm = 8x4 transpose within each 32-float block
// (k = 4*j + t <-> kappa = 8*t + j) on both operands -> LDS.128 fragments.
// R14: R13 + G1 epilogue writes g_vtp DIRECTLY (coalesced, via smem-staged
//      per-warp transpose with permuted column gather). Removes the 300MB
//      g_v->g_vtp round trip and one launch. Mainloop unchanged (2 CTAs/SM).
// ---------------------------------------------------------------------------

#define B_   32
#define NV_  512
#define NQ_  128
#define VD_  2048
#define QD_  1024
#define HK_  1536
#define HO_  8

__device__ float g_at [(size_t)B_ * NV_ * VD_];      // perm/cvt v      134MB
__device__ float g_qt [(size_t)B_ * NQ_ * QD_];      // perm/cvt q       17MB
__device__ float g_wvt[(size_t)HK_ * VD_];           // perm/cvt Wv      13MB
__device__ float g_wqt[(size_t)HK_ * QD_];           // perm/cvt Wq       6MB
__device__ float g_vtp[(size_t)B_ * NV_ * HK_];      // G1 out perm/cvt 100MB
__device__ float g_q  [(size_t)B_ * NQ_ * HK_];      // G2 out plain     25MB
__device__ float g_qh [(size_t)B_ * HO_ * NQ_ * HK_];// perm(q*hm)      201MB

#define BM 128
#define BN 128
#define KT 32
#define PROW 128                      // smem row stride bytes (XOR swizzle)
#define A_BYTES (BM * PROW)           // 16384
#define STAGE_BYTES (2 * A_BYTES)     // 32768 (A then B)
#define NSTAGE 3
#define SMEM_BYTES (NSTAGE * STAGE_BYTES)   // 98304 -> 2 CTAs/SM

__device__ __forceinline__ uint32_t rna(float x) {
    uint32_t y; asm("cvt.rna.tf32.f32 %0, %1;" : "=r"(y) : "f"(x)); return y;
}
__device__ __forceinline__ uint32_t smem_u32(const void* p) {
    uint32_t a;
    asm("{ .reg .u64 t; cvta.to.shared.u64 t, %1; cvt.u32.u64 %0, t; }"
        : "=r"(a) : "l"(p));
    return a;
}
__device__ __forceinline__ void cpa16(uint32_t dst, const void* src) {
    asm volatile("cp.async.cg.shared.global [%0], [%1], 16;"
                 :: "r"(dst), "l"(src) : "memory");
}
__device__ __forceinline__ void cpa_commit() {
    asm volatile("cp.async.commit_group;" ::: "memory");
}
__device__ __forceinline__ void cpa_wait1() {
    asm volatile("cp.async.wait_group 1;" ::: "memory");
}
__device__ __forceinline__ void mma8(float& d0, float& d1, float& d2, float& d3,
                                     uint32_t a0, uint32_t a1, uint32_t a2, uint32_t a3,
                                     uint32_t b0, uint32_t b1) {
    asm volatile(
        "mma.sync.aligned.m16n8k8.row.col.f32.tf32.tf32.f32 "
        "{%0,%1,%2,%3}, {%4,%5,%6,%7}, {%8,%9}, {%0,%1,%2,%3};"
        : "+f"(d0), "+f"(d1), "+f"(d2), "+f"(d3)
        : "r"(a0), "r"(a1), "r"(a2), "r"(a3), "r"(b0), "r"(b1));
}
// kappa -> k within a 32-block: t=kap>>3, kk=(kap>>1)&3, h=kap&1
__device__ __forceinline__ int korig(int kap) {
    return (((kap >> 1) & 3) << 3) + ((kap & 1) << 2) + (kap >> 3);
}

// --------------- pre-pass: vectorized 8x4 block transpose + cvt -----------
// dsel: 0->g_at, 1->g_qt, 2->g_wvt, 3->g_wqt
__global__ void __launch_bounds__(256)
perm_cvt(const float* __restrict__ src, int dsel, size_t nblk)
{
    const size_t idx = (size_t)blockIdx.x * blockDim.x + threadIdx.x;
    if (idx >= nblk) return;
    float* __restrict__ dstf =
        (dsel == 0) ? g_at : (dsel == 1) ? g_qt :
        (dsel == 2) ? g_wvt : g_wqt;

    const float4* __restrict__ s = (const float4*)src + idx * 8;
    float rr[32];
#pragma unroll
    for (int j = 0; j < 8; ++j) {
        const float4 t4 = s[j];
        rr[4 * j + 0] = t4.x; rr[4 * j + 1] = t4.y;
        rr[4 * j + 2] = t4.z; rr[4 * j + 3] = t4.w;
    }
    uint4* __restrict__ d = (uint4*)dstf + idx * 8;
#pragma unroll
    for (int t = 0; t < 4; ++t) {
#pragma unroll
        for (int b = 0; b < 2; ++b) {
            uint4 o;
            o.x = rna(rr[(4 * b + 0) * 4 + t]);
            o.y = rna(rr[(4 * b + 1) * 4 + t]);
            o.z = rna(rr[(4 * b + 2) * 4 + t]);
            o.w = rna(rr[(4 * b + 3) * 4 + t]);
            d[t * 2 + b] = o;
        }
    }
}

// ---- qh pass: g_qh[(z*8+h)*128+q] = perm(rna(g_q[z*128+q] * h_mat[h])) ----
__global__ void __launch_bounds__(256)
qh_cvt(const float* __restrict__ h_mat)
{
    const size_t nblk = (size_t)B_ * HO_ * NQ_ * (HK_ / 32);
    const size_t idx = (size_t)blockIdx.x * blockDim.x + threadIdx.x;
    if (idx >= nblk) return;
    const int BPR = HK_ / 32;
    const size_t row = idx / BPR;
    const int blk = (int)(idx % BPR);
    const int q = (int)(row & 127);
    const int h = (int)((row >> 7) & 7);
    const int z = (int)(row >> 10);

    const float4* __restrict__ s = (const float4*)
        (g_q + ((size_t)z * NQ_ + q) * HK_) + blk * 8;
    const float4* __restrict__ hm = (const float4*)
        (h_mat + (size_t)h * HK_) + blk * 8;

    float rr[32];
#pragma unroll
    for (int j = 0; j < 8; ++j) {
        const float4 a = s[j];
        const float4 m = hm[j];
        rr[4 * j + 0] = a.x * m.x; rr[4 * j + 1] = a.y * m.y;
        rr[4 * j + 2] = a.z * m.z; rr[4 * j + 3] = a.w * m.w;
    }
    uint4* __restrict__ d = (uint4*)(g_qh + row * HK_) + blk * 8;
#pragma unroll
    for (int t = 0; t < 4; ++t) {
#pragma unroll
        for (int b = 0; b < 2; ++b) {
            uint4 o;
            o.x = rna(rr[(4 * b + 0) * 4 + t]);
            o.y = rna(rr[(4 * b + 1) * 4 + t]);
            o.z = rna(rr[(4 * b + 2) * 4 + t]);
            o.w = rna(rr[(4 * b + 3) * 4 + t]);
            d[t * 2 + b] = o;
        }
    }
}

// ------------------------------ GEMM kernel -------------------------------
// smem layout: row r (128B) holds 8 16B segments, stored at seg^(r&7).
// sel0: A=g_at, B=g_wvt -> g_vtp DIRECT (relu+bias, rna, permuted cols,
//       coalesced via smem-staged transpose)
// sel1: A=g_qt, B=g_wqt -> g_q plain (relu+bias)
// sel2: A=g_vtp[z], B=g_qh[z] -> Cp (+h_bias[h]), h=blockIdx.y
__global__ void __launch_bounds__(256)
gemm_mma(const float* __restrict__ bias, const float* __restrict__ h_bias,
         float* __restrict__ Cp, int Ntot, int K, int sel)
{
    extern __shared__ char smem[];
    const uint32_t smb = smem_u32(smem);

    const int tid   = threadIdx.x;
    const int wid   = tid >> 5;
    const int lane  = tid & 31;
    const int group = lane >> 2;
    const int tig   = lane & 3;
    const int warp_m = (wid & 1) * 64;
    const int warp_n = (wid >> 1) * 32;

    const int bm = blockIdx.x * BM;
    const int bn = blockIdx.y * BN;
    const int z  = blockIdx.z;
    const int mode = (sel == 2);

    const float* __restrict__ Abase =
        (sel == 0) ? g_at : (sel == 1) ? g_qt : g_vtp;
    const float* __restrict__ Bbase =
        (sel == 0) ? g_wvt : (sel == 1) ? g_wqt : g_qh;

    const float* __restrict__ Ag = Abase +
        ((size_t)(mode ? z * NV_ : 0) + bm) * K;
    const float* __restrict__ Bg = Bbase +
        ((size_t)(mode ? z * (HO_ * NQ_) : 0) + bn) * K;

    const int r0 = tid >> 3;                  // staging row 0..31
    const int sseg = tid & 7;                 // staging segment 0..7
    const int s4 = sseg * 4;                  // segment offset (floats)
    const uint32_t stg_off =
        (uint32_t)(r0 * PROW + ((sseg ^ (r0 & 7)) << 4));

    float acc[4][4][4];
#pragma unroll
    for (int i = 0; i < 4; ++i)
#pragma unroll
        for (int j = 0; j < 4; ++j)
#pragma unroll
            for (int l = 0; l < 4; ++l) acc[i][j][l] = 0.f;

    const int NC = K / KT;

    // prologue: stages 0 and 1
#pragma unroll
    for (int s = 0; s < 2; ++s) {
        const uint32_t sb = smb + s * STAGE_BYTES;
        const int k0 = s * KT;
#pragma unroll
        for (int i = 0; i < 4; ++i) {
            const int r = r0 + 32 * i;        // r&7 == r0&7
            cpa16(sb + stg_off + i * 32 * PROW,
                  Ag + (size_t)r * K + k0 + s4);
            cpa16(sb + A_BYTES + stg_off + i * 32 * PROW,
                  Bg + (size_t)r * K + k0 + s4);
        }
        cpa_commit();
    }

    for (int c = 0; c < NC; ++c) {
        cpa_wait1();
        __syncthreads();

        if (c + 2 < NC) {
            const uint32_t sb = smb + ((c + 2) % NSTAGE) * STAGE_BYTES;
            const int k0 = (c + 2) * KT;
#pragma unroll
            for (int i = 0; i < 4; ++i) {
                const int r = r0 + 32 * i;
                cpa16(sb + stg_off + i * 32 * PROW,
                      Ag + (size_t)r * K + k0 + s4);
                cpa16(sb + A_BYTES + stg_off + i * 32 * PROW,
                      Bg + (size_t)r * K + k0 + s4);
            }
        }
        cpa_commit();

        const char* sa = smem + (c % NSTAGE) * STAGE_BYTES;
        const char* sbuf = sa + A_BYTES;
#pragma unroll
        for (int hf = 0; hf < 2; ++hf) {
            const int fsw = ((tig * 2 + hf) ^ group) << 4;
#pragma unroll
            for (int mp = 0; mp < 2; ++mp) {
                uint4 aL0, aH0, aL1, aH1;
                {
                    const int m0 = warp_m + (mp * 2 + 0) * 16 + group;
                    const int m1 = warp_m + (mp * 2 + 1) * 16 + group;
                    aL0 = *(const uint4*)(sa + m0 * PROW + fsw);
                    aH0 = *(const uint4*)(sa + (m0 + 8) * PROW + fsw);
                    aL1 = *(const uint4*)(sa + m1 * PROW + fsw);
                    aH1 = *(const uint4*)(sa + (m1 + 8) * PROW + fsw);
                }
#pragma unroll
                for (int nf = 0; nf < 4; ++nf) {
                    const uint4 bv = *(const uint4*)(sbuf +
                        (warp_n + nf * 8 + group) * PROW + fsw);
                    const int mf0 = mp * 2, mf1 = mp * 2 + 1;
                    mma8(acc[mf0][nf][0], acc[mf0][nf][1],
                         acc[mf0][nf][2], acc[mf0][nf][3],
                         aL0.x, aH0.x, aL0.y, aH0.y, bv.x, bv.y);
                    mma8(acc[mf0][nf][0], acc[mf0][nf][1],
                         acc[mf0][nf][2], acc[mf0][nf][3],
                         aL0.z, aH0.z, aL0.w, aH0.w, bv.z, bv.w);
                    mma8(acc[mf1][nf][0], acc[mf1][nf][1],
                         acc[mf1][nf][2], acc[mf1][nf][3],
                         aL1.x, aH1.x, aL1.y, aH1.y, bv.x, bv.y);
                    mma8(acc[mf1][nf][0], acc[mf1][nf][1],
                         acc[mf1][nf][2], acc[mf1][nf][3],
                         aL1.z, aH1.z, aL1.w, aH1.w, bv.z, bv.w);
                }
            }
        }
        __syncthreads();
    }

    // ---------------------------- epilogue --------------------------------
    if (sel == 0) {
        // fused permuted write: stage warp's 64x32 block in smem (stride 33),
        // gather permuted columns per row, write coalesced uint4 to g_vtp.
        float* tr = (float*)smem + wid * (64 * 33);
#pragma unroll
        for (int nf = 0; nf < 4; ++nf) {
            const int nc = nf * 8 + 2 * tig;           // warp-local col
            const int gn = bn + warp_n + nc;
            const float b0 = __ldg(&bias[gn]);
            const float b1 = __ldg(&bias[gn + 1]);
#pragma unroll
            for (int mf = 0; mf < 4; ++mf) {
                const int rl = mf * 16 + group;        // warp-local row
                tr[rl * 33 + nc]           = fmaxf(acc[mf][nf][0] + b0, 0.f);
                tr[rl * 33 + nc + 1]       = fmaxf(acc[mf][nf][1] + b1, 0.f);
                tr[(rl + 8) * 33 + nc]     = fmaxf(acc[mf][nf][2] + b0, 0.f);
                tr[(rl + 8) * 33 + nc + 1] = fmaxf(acc[mf][nf][3] + b1, 0.f);
            }
        }
        __syncwarp();
        uint32_t* __restrict__ C = (uint32_t*)g_vtp;
        const int cbase = bn + warp_n;                 // 32-aligned col base
#pragma unroll
        for (int rr2 = 0; rr2 < 2; ++rr2) {
            const int rl = lane + rr2 * 32;            // warp-local row
            const int gm = bm + warp_m + rl;
            const float* trow = tr + rl * 33;
#pragma unroll
            for (int u = 0; u < 8; ++u) {              // 8 x uint4
                uint4 o;
                o.x = rna(trow[korig(4 * u + 0)]);
                o.y = rna(trow[korig(4 * u + 1)]);
                o.z = rna(trow[korig(4 * u + 2)]);
                o.w = rna(trow[korig(4 * u + 3)]);
                *(uint4*)(C + (size_t)gm * Ntot + cbase + 4 * u) = o;
            }
        }
    } else if (sel == 1) {
        float* __restrict__ C = g_q;
#pragma unroll
        for (int nf = 0; nf < 4; ++nf) {
            const int gn = bn + warp_n + nf * 8 + 2 * tig;
            const float b0 = __ldg(&bias[gn]);
            const float b1 = __ldg(&bias[gn + 1]);
#pragma unroll
            for (int mf = 0; mf < 4; ++mf) {
                const int gm = bm + warp_m + mf * 16 + group;
                float2 lo, hi;
                lo.x = fmaxf(acc[mf][nf][0] + b0, 0.f);
                lo.y = fmaxf(acc[mf][nf][1] + b1, 0.f);
                hi.x = fmaxf(acc[mf][nf][2] + b0, 0.f);
                hi.y = fmaxf(acc[mf][nf][3] + b1, 0.f);
                *(float2*)(C + (size_t)gm * Ntot + gn)       = lo;
                *(float2*)(C + (size_t)(gm + 8) * Ntot + gn) = hi;
            }
        }
    } else {
        const int h = blockIdx.y;
        const float hb = __ldg(&h_bias[h]);
        float* __restrict__ C = Cp + ((size_t)(z * HO_ + h) * NV_) * NQ_;
#pragma unroll
        for (int nf = 0; nf < 4; ++nf) {
            const int qn = warp_n + nf * 8 + 2 * tig;
#pragma unroll
            for (int mf = 0; mf < 4; ++mf) {
                const int vm = bm + warp_m + mf * 16 + group;
                float2 lo, hi;
                lo.x = acc[mf][nf][0] + hb;
                lo.y = acc[mf][nf][1] + hb;
                hi.x = acc[mf][nf][2] + hb;
                hi.y = acc[mf][nf][3] + hb;
                *(float2*)(C + (size_t)vm * NQ_ + qn)       = lo;
                *(float2*)(C + (size_t)(vm + 8) * NQ_ + qn) = hi;
            }
        }
    }
}

// ---------------------------------------------------------------------------
// inputs: v, q, Wv, bv, Wq, bq, h_mat, h_bias ; output fp32 (32,8,512,128)
// ---------------------------------------------------------------------------
static inline unsigned bgrid(size_t nblk) { return (unsigned)((nblk + 255) / 256); }

extern "C" void kernel_launch(void* const* d_in, const int* in_sizes, int n_in,
                              void* d_out, int out_size)
{
    const float* v      = (const float*)d_in[0];
    const float* q      = (const float*)d_in[1];
    const float* Wv     = (const float*)d_in[2];
    const float* bv     = (const float*)d_in[3];
    const float* Wq     = (const float*)d_in[4];
    const float* bq     = (const float*)d_in[5];
    const float* h_mat  = (const float*)d_in[6];
    const float* h_bias = (const float*)d_in[7];
    float* out = (float*)d_out;

    cudaFuncSetAttribute(gemm_mma, cudaFuncAttributeMaxDynamicSharedMemorySize,
                         SMEM_BYTES);

    const size_t blk_v  = (size_t)B_ * NV_ * VD_ / 32;
    const size_t blk_q  = (size_t)B_ * NQ_ * QD_ / 32;
    const size_t blk_wv = (size_t)HK_ * VD_ / 32;
    const size_t blk_wq = (size_t)HK_ * QD_ / 32;
    const size_t blk_qh = (size_t)B_ * HO_ * NQ_ * (HK_ / 32);

    perm_cvt<<<bgrid(blk_v),  256>>>(v,  0, blk_v);       // 0
    perm_cvt<<<bgrid(blk_wv), 256>>>(Wv, 2, blk_wv);      // 1
    perm_cvt<<<bgrid(blk_q),  256>>>(q,  1, blk_q);       // 2
    perm_cvt<<<bgrid(blk_wq), 256>>>(Wq, 3, blk_wq);      // 3
    // G2: q-proj -> g_q  M=4096 N=1536 K=1024
    gemm_mma<<<dim3((B_ * NQ_) / BM, HK_ / BN, 1), 256, SMEM_BYTES>>>(
        bq, nullptr, nullptr, HK_, QD_, 1);               // 4
    // G1: v-proj -> g_vtp (fused perm)  M=16384 N=1536 K=2048   // 5
    gemm_mma<<<dim3((B_ * NV_) / BM, HK_ / BN, 1), 256, SMEM_BYTES>>>(
        bv, nullptr, nullptr, HK_, VD_, 0);
    qh_cvt<<<bgrid(blk_qh), 256>>>(h_mat);                // 6
    // G3: bilinear -> out  per z: M=512 N=1024(8h x 128q) K=1536
    gemm_mma<<<dim3(NV_ / BM, (HO_ * NQ_) / BN, B_), 256, SMEM_BYTES>>>(
        nullptr, h_bias, out, HO_ * NQ_, HK_, 2);         // 7
}